// round 2
// baseline (speedup 1.0000x reference)
#include <cuda_runtime.h>
#include <math.h>

// ---------------- problem constants ----------------
#define NB    1024
#define MT    64
#define DD    512
#define NH    8
#define HD    64
#define DEPTH 4
#define FF    2048
#define NOBJ  8192
#define NTRI  10240
#define BMT   (NB*MT)   // 65536 rows

// ---------------- scratch (static device memory; no allocations) ----------------
__device__ float g_x   [BMT*DD];
__device__ float g_h   [BMT*DD];
__device__ float g_q   [BMT*DD];
__device__ float g_k   [BMT*DD];
__device__ float g_v   [BMT*DD];
__device__ float g_attn[BMT*DD];
__device__ float g_ff  [(size_t)BMT*FF];
__device__ float g_boxh   [NOBJ*DD];
__device__ float g_objbase[NOBJ*DD];
__device__ float g_objtok [NOBJ*DD];
__device__ unsigned char g_mask[BMT];
__device__ int   g_first[NB];

__device__ __forceinline__ float gelu_f(float x) {
    return 0.5f * x * (1.0f + erff(x * 0.70710678118654752440f));
}

// ---------------- 128x128x8 fp32 GEMM, 256 threads, 8x8 per thread ----------------
// C[M,N] = A[M,K] @ B[K,N] (+bias[n]) (gelu?) (+res[m,n])
#define GBM 128
#define GBN 128
#define GBK 8

template<bool GELU>
__global__ void __launch_bounds__(256, 2) gemm_k(
    const float* __restrict__ A, const float* __restrict__ Bm,
    const float* __restrict__ bias, const float* __restrict__ res,
    float* __restrict__ C, int M, int N, int K)
{
    __shared__ float As[GBK][GBM];
    __shared__ float Bs[GBK][GBN];
    const int tid = threadIdx.x;
    const int tr  = tid >> 4;          // 0..15  -> rows tr*8..tr*8+7
    const int tc  = tid & 15;          // 0..15  -> cols tc*8..tc*8+7
    const int bm  = blockIdx.x * GBM;
    const int bn  = blockIdx.y * GBN;

    const int am  = tid >> 1;          // 0..127 : A row within tile
    const int ak  = (tid & 1) * 4;     // 0 or 4 : A k-offset
    const int bk  = tid >> 5;          // 0..7   : B row within tile
    const int bnn = (tid & 31) * 4;    // 0..124 : B col offset

    float acc[8][8];
#pragma unroll
    for (int i = 0; i < 8; i++)
#pragma unroll
        for (int j = 0; j < 8; j++) acc[i][j] = 0.f;

    const float* Aptr = A  + (size_t)(bm + am) * K + ak;
    const float* Bptr = Bm + (size_t)bk * N + bn + bnn;

    for (int k0 = 0; k0 < K; k0 += GBK) {
        float4 av = *(const float4*)(Aptr + k0);
        float4 bv = *(const float4*)(Bptr + (size_t)k0 * N);
        As[ak + 0][am] = av.x;
        As[ak + 1][am] = av.y;
        As[ak + 2][am] = av.z;
        As[ak + 3][am] = av.w;
        *(float4*)&Bs[bk][bnn] = bv;
        __syncthreads();
#pragma unroll
        for (int kk = 0; kk < GBK; kk++) {
            float a[8], b[8];
            *(float4*)&a[0] = *(const float4*)&As[kk][tr * 8];
            *(float4*)&a[4] = *(const float4*)&As[kk][tr * 8 + 4];
            *(float4*)&b[0] = *(const float4*)&Bs[kk][tc * 8];
            *(float4*)&b[4] = *(const float4*)&Bs[kk][tc * 8 + 4];
#pragma unroll
            for (int i = 0; i < 8; i++)
#pragma unroll
                for (int j = 0; j < 8; j++)
                    acc[i][j] = fmaf(a[i], b[j], acc[i][j]);
        }
        __syncthreads();
    }

#pragma unroll
    for (int i = 0; i < 8; i++) {
        int m = bm + tr * 8 + i;
        size_t rowoff = (size_t)m * N + bn;
#pragma unroll
        for (int j0 = 0; j0 < 8; j0 += 4) {
            float4 o;
            float* po = (float*)&o;
#pragma unroll
            for (int j = 0; j < 4; j++) {
                int n = tc * 8 + j0 + j;
                float vv = acc[i][j0 + j];
                if (bias) vv += bias[bn + n];
                if (GELU) vv = gelu_f(vv);
                if (res)  vv += res[rowoff + n];
                po[j] = vv;
            }
            *(float4*)(C + rowoff + tc * 8 + j0) = o;
        }
    }
}

// ---------------- LayerNorm: one block per row, 128 threads ----------------
__global__ void __launch_bounds__(128) ln_k(
    const float* __restrict__ x, const float* __restrict__ g,
    const float* __restrict__ bvec, float* __restrict__ out)
{
    int row = blockIdx.x;
    const float* xr = x + (size_t)row * DD;
    float*       orow = out + (size_t)row * DD;
    int tid = threadIdx.x;
    float4 v = *(const float4*)(xr + tid * 4);
    float s  = v.x + v.y + v.z + v.w;
    float sq = v.x*v.x + v.y*v.y + v.z*v.z + v.w*v.w;
#pragma unroll
    for (int off = 16; off; off >>= 1) {
        s  += __shfl_xor_sync(0xffffffffu, s,  off);
        sq += __shfl_xor_sync(0xffffffffu, sq, off);
    }
    __shared__ float ss[4], ssq[4];
    int w = tid >> 5, l = tid & 31;
    if (l == 0) { ss[w] = s; ssq[w] = sq; }
    __syncthreads();
    s  = ss[0] + ss[1] + ss[2] + ss[3];
    sq = ssq[0] + ssq[1] + ssq[2] + ssq[3];
    float mean = s * (1.f / DD);
    float var  = sq * (1.f / DD) - mean * mean;
    float rstd = rsqrtf(var + 1e-5f);
    float4 gv = *(const float4*)(g    + tid * 4);
    float4 bb = *(const float4*)(bvec + tid * 4);
    float4 o;
    o.x = (v.x - mean) * rstd * gv.x + bb.x;
    o.y = (v.y - mean) * rstd * gv.y + bb.y;
    o.z = (v.z - mean) * rstd * gv.z + bb.z;
    o.w = (v.w - mean) * rstd * gv.w + bb.w;
    *(float4*)(orow + tid * 4) = o;
}

// ---------------- box MLP stage 1: gelu(LN(boxes@bw1+bb1)) ----------------
__global__ void __launch_bounds__(128) box_k(
    const float* __restrict__ boxes, const float* __restrict__ bw1,
    const float* __restrict__ bb1, const float* __restrict__ blg,
    const float* __restrict__ blb, float* __restrict__ out)
{
    int r = blockIdx.x;
    float b0 = boxes[r * 4 + 0], b1 = boxes[r * 4 + 1];
    float b2 = boxes[r * 4 + 2], b3 = boxes[r * 4 + 3];
    int tid = threadIdx.x;
    int d0 = tid * 4;
    float4 w0 = *(const float4*)(bw1 + d0);
    float4 w1 = *(const float4*)(bw1 + 512  + d0);
    float4 w2 = *(const float4*)(bw1 + 1024 + d0);
    float4 w3 = *(const float4*)(bw1 + 1536 + d0);
    float4 bbv = *(const float4*)(bb1 + d0);
    float t[4];
    t[0] = bbv.x + b0*w0.x + b1*w1.x + b2*w2.x + b3*w3.x;
    t[1] = bbv.y + b0*w0.y + b1*w1.y + b2*w2.y + b3*w3.y;
    t[2] = bbv.z + b0*w0.z + b1*w1.z + b2*w2.z + b3*w3.z;
    t[3] = bbv.w + b0*w0.w + b1*w1.w + b2*w2.w + b3*w3.w;
    float s  = t[0]+t[1]+t[2]+t[3];
    float sq = t[0]*t[0]+t[1]*t[1]+t[2]*t[2]+t[3]*t[3];
#pragma unroll
    for (int off = 16; off; off >>= 1) {
        s  += __shfl_xor_sync(0xffffffffu, s,  off);
        sq += __shfl_xor_sync(0xffffffffu, sq, off);
    }
    __shared__ float ss[4], ssq[4];
    int w = tid >> 5, l = tid & 31;
    if (l == 0) { ss[w] = s; ssq[w] = sq; }
    __syncthreads();
    s  = ss[0] + ss[1] + ss[2] + ss[3];
    sq = ssq[0] + ssq[1] + ssq[2] + ssq[3];
    float mean = s * (1.f / DD);
    float var  = sq * (1.f / DD) - mean * mean;
    float rstd = rsqrtf(var + 1e-5f);
    float4 gv = *(const float4*)(blg + d0);
    float4 bv = *(const float4*)(blb + d0);
    float4 o;
    o.x = gelu_f((t[0] - mean) * rstd * gv.x + bv.x);
    o.y = gelu_f((t[1] - mean) * rstd * gv.y + bv.y);
    o.z = gelu_f((t[2] - mean) * rstd * gv.z + bv.z);
    o.w = gelu_f((t[3] - mean) * rstd * gv.w + bv.w);
    *(float4*)(out + (size_t)r * DD + d0) = o;
}

// ---------------- gather obj embeddings ----------------
__global__ void __launch_bounds__(128) gather_k(
    const int* __restrict__ objs, const float* __restrict__ obj_emb,
    float* __restrict__ out)
{
    int r = blockIdx.x;
    int o = objs[r];
    float4 v = *(const float4*)(obj_emb + (size_t)o * DD + threadIdx.x * 4);
    *(float4*)(out + (size_t)r * DD + threadIdx.x * 4) = v;
}

// ---------------- first[i] = lower_bound(triple_to_img, i) ----------------
__global__ void first_k(const int* __restrict__ t2i, int* __restrict__ first)
{
    int i = blockIdx.x * blockDim.x + threadIdx.x;
    if (i >= NB) return;
    int lo = 0, hi = NTRI;
    while (lo < hi) {
        int mid = (lo + hi) >> 1;
        if (t2i[mid] < i) lo = mid + 1; else hi = mid;
    }
    first[i] = lo;
}

// ---------------- scatter triples into token grid ----------------
__global__ void __launch_bounds__(128) scatter_k(
    const int* __restrict__ triples, const int* __restrict__ t2i,
    const int* __restrict__ first, const float* __restrict__ objtok,
    const float* __restrict__ pred_emb, float* __restrict__ x,
    unsigned char* __restrict__ mask)
{
    int t = blockIdx.x;
    int j = blockIdx.y;
    int img = t2i[t];
    int pos = t - first[img];
    int slot = pos * 3 + j;
    if (slot >= MT) return;
    const float* src;
    if (j == 0)      src = objtok   + (size_t)triples[t * 3 + 0] * DD;
    else if (j == 1) src = pred_emb + (size_t)triples[t * 3 + 1] * DD;
    else             src = objtok   + (size_t)triples[t * 3 + 2] * DD;
    float* dst = x + ((size_t)img * MT + slot) * DD;
    int tid = threadIdx.x;
    *(float4*)(dst + tid * 4) = *(const float4*)(src + tid * 4);
    if (tid == 0) mask[img * MT + slot] = 1;
}

// ---------------- attention: one block per (b, h) ----------------
__global__ void __launch_bounds__(256) attn_k(
    const float* __restrict__ q, const float* __restrict__ k,
    const float* __restrict__ v, const unsigned char* __restrict__ mask,
    float* __restrict__ out)
{
    __shared__ float sA[64][65];   // q, later v
    __shared__ float sB[64][65];   // k, later probs
    int b = blockIdx.x, h = blockIdx.y;
    int tid = threadIdx.x;
    int tx = tid & 15, ty = tid >> 4;
    const size_t base = ((size_t)b * MT) * DD + (size_t)h * HD;

#pragma unroll
    for (int i = 0; i < 16; i++) {
        int idx = tid + i * 256;
        int m = idx >> 6, d = idx & 63;
        sA[m][d] = q[base + (size_t)m * DD + d];
        sB[m][d] = k[base + (size_t)m * DD + d];
    }
    __syncthreads();

    bool mv[4];
#pragma unroll
    for (int j = 0; j < 4; j++) mv[j] = mask[b * MT + tx * 4 + j] != 0;

    float sc[4][4];
#pragma unroll
    for (int i = 0; i < 4; i++)
#pragma unroll
        for (int j = 0; j < 4; j++) sc[i][j] = 0.f;

    for (int d = 0; d < 64; d++) {
        float a[4], bb[4];
#pragma unroll
        for (int i = 0; i < 4; i++) a[i]  = sA[ty * 4 + i][d];
#pragma unroll
        for (int j = 0; j < 4; j++) bb[j] = sB[tx * 4 + j][d];
#pragma unroll
        for (int i = 0; i < 4; i++)
#pragma unroll
            for (int j = 0; j < 4; j++)
                sc[i][j] = fmaf(a[i], bb[j], sc[i][j]);
    }
#pragma unroll
    for (int i = 0; i < 4; i++)
#pragma unroll
        for (int j = 0; j < 4; j++)
            sc[i][j] = mv[j] ? sc[i][j] * 0.125f : -1e9f;

    // softmax across the 16-lane groups (lanes with equal ty share a half-warp)
#pragma unroll
    for (int i = 0; i < 4; i++) {
        float mx = fmaxf(fmaxf(sc[i][0], sc[i][1]), fmaxf(sc[i][2], sc[i][3]));
#pragma unroll
        for (int off = 8; off; off >>= 1)
            mx = fmaxf(mx, __shfl_xor_sync(0xffffffffu, mx, off));
        float sum = 0.f;
#pragma unroll
        for (int j = 0; j < 4; j++) {
            sc[i][j] = expf(sc[i][j] - mx);
            sum += sc[i][j];
        }
#pragma unroll
        for (int off = 8; off; off >>= 1)
            sum += __shfl_xor_sync(0xffffffffu, sum, off);
        float inv = 1.0f / sum;
#pragma unroll
        for (int j = 0; j < 4; j++) sc[i][j] *= inv;
    }
    __syncthreads();

    // sB <- probs, sA <- v
#pragma unroll
    for (int i = 0; i < 4; i++)
#pragma unroll
        for (int j = 0; j < 4; j++)
            sB[ty * 4 + i][tx * 4 + j] = sc[i][j];
#pragma unroll
    for (int i = 0; i < 16; i++) {
        int idx = tid + i * 256;
        int m = idx >> 6, d = idx & 63;
        sA[m][d] = v[base + (size_t)m * DD + d];
    }
    __syncthreads();

    float o[4][4];
#pragma unroll
    for (int i = 0; i < 4; i++)
#pragma unroll
        for (int j = 0; j < 4; j++) o[i][j] = 0.f;
    for (int kk = 0; kk < 64; kk++) {
        float p[4], vv[4];
#pragma unroll
        for (int i = 0; i < 4; i++) p[i]  = sB[ty * 4 + i][kk];
#pragma unroll
        for (int j = 0; j < 4; j++) vv[j] = sA[kk][tx * 4 + j];
#pragma unroll
        for (int i = 0; i < 4; i++)
#pragma unroll
            for (int j = 0; j < 4; j++)
                o[i][j] = fmaf(p[i], vv[j], o[i][j]);
    }
#pragma unroll
    for (int i = 0; i < 4; i++)
#pragma unroll
        for (int j = 0; j < 4; j++)
            out[base + (size_t)(ty * 4 + i) * DD + tx * 4 + j] = o[i][j];
}

// ---------------- host launcher ----------------
extern "C" void kernel_launch(void* const* d_in, const int* in_sizes, int n_in,
                              void* d_out, int out_size)
{
    (void)in_sizes; (void)n_in; (void)out_size;
    const int*   objs    = (const int*)  d_in[0];
    const float* boxes   = (const float*)d_in[1];
    const int*   triples = (const int*)  d_in[2];
    const int*   t2i     = (const int*)  d_in[4];
    const float* obj_emb = (const float*)d_in[5];
    const float* pred_emb= (const float*)d_in[6];
    const float* bw1     = (const float*)d_in[7];
    const float* bb1     = (const float*)d_in[8];
    const float* blg     = (const float*)d_in[9];
    const float* blb     = (const float*)d_in[10];
    const float* bw2     = (const float*)d_in[11];
    const float* bb2     = (const float*)d_in[12];
    const float* ln1g    = (const float*)d_in[13];
    const float* ln1b    = (const float*)d_in[14];
    const float* wq      = (const float*)d_in[15];
    const float* bq      = (const float*)d_in[16];
    const float* wk      = (const float*)d_in[17];
    const float* bk      = (const float*)d_in[18];
    const float* wv      = (const float*)d_in[19];
    const float* bv      = (const float*)d_in[20];
    const float* wo      = (const float*)d_in[21];
    const float* bo      = (const float*)d_in[22];
    const float* ln2g    = (const float*)d_in[23];
    const float* ln2b    = (const float*)d_in[24];
    const float* wf1     = (const float*)d_in[25];
    const float* bf1     = (const float*)d_in[26];
    const float* wf2     = (const float*)d_in[27];
    const float* bf2     = (const float*)d_in[28];
    float* outp = (float*)d_out;

    float *x, *h, *q, *k, *v, *attn, *ff, *boxh, *objbase, *objtok;
    unsigned char* mask;
    int* first;
    cudaGetSymbolAddress((void**)&x,       g_x);
    cudaGetSymbolAddress((void**)&h,       g_h);
    cudaGetSymbolAddress((void**)&q,       g_q);
    cudaGetSymbolAddress((void**)&k,       g_k);
    cudaGetSymbolAddress((void**)&v,       g_v);
    cudaGetSymbolAddress((void**)&attn,    g_attn);
    cudaGetSymbolAddress((void**)&ff,      g_ff);
    cudaGetSymbolAddress((void**)&boxh,    g_boxh);
    cudaGetSymbolAddress((void**)&objbase, g_objbase);
    cudaGetSymbolAddress((void**)&objtok,  g_objtok);
    cudaGetSymbolAddress((void**)&mask,    g_mask);
    cudaGetSymbolAddress((void**)&first,   g_first);

    // prologue: box MLP + obj embedding
    box_k<<<NOBJ, 128>>>(boxes, bw1, bb1, blg, blb, boxh);
    gather_k<<<NOBJ, 128>>>(objs, obj_emb, objbase);
    {
        dim3 grid(NOBJ / GBM, DD / GBN);
        gemm_k<false><<<grid, 256>>>(boxh, bw2, bb2, objbase, objtok, NOBJ, DD, DD);
    }
    first_k<<<(NB + 127) / 128, 128>>>(t2i, first);
    cudaMemsetAsync(x, 0, (size_t)BMT * DD * sizeof(float));
    cudaMemsetAsync(mask, 0, BMT);
    {
        dim3 grid(NTRI, 3);
        scatter_k<<<grid, 128>>>(triples, t2i, first, objtok, pred_emb, x, mask);
    }

    // transformer layers
    dim3 gD(BMT / GBM, DD / GBN);     // (512, 4)
    dim3 gF(BMT / GBM, FF / GBN);     // (512, 16)
    for (int l = 0; l < DEPTH; l++) {
        size_t wD = (size_t)l * DD * DD;
        size_t wF1 = (size_t)l * DD * FF;
        size_t wF2 = (size_t)l * FF * DD;
        ln_k<<<BMT, 128>>>(x, ln1g + l * DD, ln1b + l * DD, h);
        gemm_k<false><<<gD, 256>>>(h, wq + wD, bq + l * DD, nullptr, q, BMT, DD, DD);
        gemm_k<false><<<gD, 256>>>(h, wk + wD, bk + l * DD, nullptr, k, BMT, DD, DD);
        gemm_k<false><<<gD, 256>>>(h, wv + wD, bv + l * DD, nullptr, v, BMT, DD, DD);
        {
            dim3 ga(NB, NH);
            attn_k<<<ga, 256>>>(q, k, v, mask, attn);
        }
        gemm_k<false><<<gD, 256>>>(attn, wo + wD, bo + l * DD, x, x, BMT, DD, DD);
        ln_k<<<BMT, 128>>>(x, ln2g + l * DD, ln2b + l * DD, h);
        gemm_k<true><<<gF, 256>>>(h, wf1 + wF1, bf1 + l * FF, nullptr, ff, BMT, FF, DD);
        float* cdst = (l == DEPTH - 1) ? outp : x;
        gemm_k<false><<<gD, 256>>>(ff, wf2 + wF2, bf2 + l * DD, x, cdst, BMT, DD, FF);
    }
}

// round 6
// speedup vs baseline: 2.4405x; 2.4405x over previous
#include <cuda_runtime.h>
#include <cuda_bf16.h>
#include <math.h>
#include <stdint.h>

// ---------------- problem constants ----------------
#define NB    1024
#define MT    64
#define DD    512
#define NH    8
#define HD    64
#define DEPTH 4
#define FF    2048
#define NOBJ  8192
#define NTRI  10240
#define BMT   (NB*MT)   // 65536 rows
#define QS    1536      // packed qkv row stride

// ---------------- static scratch ----------------
#define W_TOT 12845056   // 512*512 + 4*(1536*512 + 512*512 + 2048*512 + 512*2048)
__device__ __nv_bfloat16 g_whi[W_TOT];
__device__ __nv_bfloat16 g_wlo[W_TOT];
__device__ float g_bqkv[DEPTH*QS];
__device__ float g_x   [BMT*DD];
__device__ float g_h   [BMT*DD];
__device__ float g_qkv [(size_t)BMT*QS];
__device__ float g_attn[BMT*DD];
__device__ float g_ff  [(size_t)BMT*FF];
__device__ float g_boxh   [NOBJ*DD];
__device__ float g_objbase[NOBJ*DD];
__device__ float g_objtok [NOBJ*DD];
__device__ unsigned char g_mask[BMT];
__device__ int   g_first[NB];

// weight pool offsets (bf16 elements)
#define OFF_BW2 0
#define LYR_STRIDE 3145728
#define OFF_L(l)   (262144 + (l)*LYR_STRIDE)
#define OFF_QKV(l) OFF_L(l)
#define OFF_WO(l)  (OFF_L(l)+786432)
#define OFF_F1(l)  (OFF_L(l)+1048576)
#define OFF_F2(l)  (OFF_L(l)+2097152)

__device__ __forceinline__ float gelu_f(float x) {
    return 0.5f * x * (1.0f + erff(x * 0.70710678118654752440f));
}

__device__ __forceinline__ uint32_t smem_u32(const void* p) {
    uint32_t a;
    asm("{ .reg .u64 t; cvta.to.shared.u64 t, %1; cvt.u32.u64 %0, t; }" : "=r"(a) : "l"(p));
    return a;
}

// ---------------- warp-level MMA primitives (family-wide, sm_80+) ----------------
__device__ __forceinline__ void ldm4(uint32_t* r, uint32_t addr) {
    asm volatile("ldmatrix.sync.aligned.m8n8.x4.shared.b16 {%0,%1,%2,%3}, [%4];"
        : "=r"(r[0]), "=r"(r[1]), "=r"(r[2]), "=r"(r[3]) : "r"(addr));
}
__device__ __forceinline__ void mma16816(float* d, const uint32_t* a, const uint32_t* b) {
    asm volatile("mma.sync.aligned.m16n8k16.row.col.f32.bf16.bf16.f32 "
        "{%0,%1,%2,%3}, {%4,%5,%6,%7}, {%8,%9}, {%0,%1,%2,%3};"
        : "+f"(d[0]), "+f"(d[1]), "+f"(d[2]), "+f"(d[3])
        : "r"(a[0]), "r"(a[1]), "r"(a[2]), "r"(a[3]), "r"(b[0]), "r"(b[1]));
}

// ---------------- GEMM: mma.sync bf16 3-term split ----------------
// C[M,N] = A[M,K](fp32) @ B^T (B given as [N][K] bf16 hi/lo) + bias (+gelu) (+res)
// Tile 128x128, BK=32, 8 warps (2x4), warp tile 64x32, double-buffered smem.
#define BM 128
#define BN 128
#define BK 32
#define LDE 40            // padded smem row stride in elements (80 B)
#define AH_OFF 0
#define AL_OFF 10240
#define BH_OFF 20480
#define BL_OFF 30720
#define STG_SZ 40960
#define GSM_TOTAL (2*STG_SZ)   // 81920 B

template<bool GELU>
__global__ void __launch_bounds__(256, 1) gemm_mma(
    const float* __restrict__ A, const __nv_bfloat16* __restrict__ Bhi,
    const __nv_bfloat16* __restrict__ Blo, const float* __restrict__ bias,
    const float* __restrict__ res, float* __restrict__ C, int K, int ldc)
{
    extern __shared__ char sm[];
    const uint32_t smb = smem_u32(sm);
    const int tid  = threadIdx.x;
    const int lane = tid & 31;
    const int wid  = tid >> 5;
    const int wm   = (wid & 1) * 64;
    const int wn   = (wid >> 1) * 32;
    const int bn   = blockIdx.x * BN;
    const int bm   = blockIdx.y * BM;

    // ldmatrix per-lane address components
    const int aRow = lane & 15;
    const int aK   = (lane >> 4) << 3;
    const int bRow = (lane & 7) + ((lane >> 4) << 3);
    const int bK   = ((lane >> 3) & 1) << 3;

    // load-stage register staging
    float a_ld[16];
    uint4 bh_ld[2], bl_ld[2];

    // loader index precompute
    const int ar  = (tid + 0) >> 3;        // rows for A float4 chunks: idx>>3
    const int ac4 = tid & 7;
    const int br  = tid >> 2;              // rows for B uint4 chunks
    const int bc  = tid & 3;

    float d[4][4][4];
#pragma unroll
    for (int i = 0; i < 4; i++)
#pragma unroll
        for (int j = 0; j < 4; j++)
#pragma unroll
            for (int u = 0; u < 4; u++) d[i][j][u] = 0.f;

    const int NKT = K >> 5;   // BK=32 chunks

    // ---- global load (k-chunk kt) into registers ----
    auto gload = [&](int kt) {
        const int k0 = kt << 5;
#pragma unroll
        for (int i = 0; i < 4; i++) {
            int idx = tid + i * 256;
            int row = idx >> 3, c4 = idx & 7;
            const float4 v = *(const float4*)(A + (size_t)(bm + row) * K + k0 + c4 * 4);
            a_ld[i*4+0] = v.x; a_ld[i*4+1] = v.y; a_ld[i*4+2] = v.z; a_ld[i*4+3] = v.w;
        }
#pragma unroll
        for (int i = 0; i < 2; i++) {
            int idx = tid + i * 256;
            int row = idx >> 2, c16 = idx & 3;
            size_t gi = (size_t)(bn + row) * K + k0 + c16 * 8;
            bh_ld[i] = *(const uint4*)(Bhi + gi);
            bl_ld[i] = *(const uint4*)(Blo + gi);
        }
    };

    // ---- store staged registers into smem stage s ----
    auto sstore = [&](int s) {
        char* base = sm + s * STG_SZ;
#pragma unroll
        for (int i = 0; i < 4; i++) {
            int idx = tid + i * 256;
            int row = idx >> 3, c4 = idx & 7;
            uint32_t hp[2], lp[2];
#pragma unroll
            for (int u = 0; u < 2; u++) {
                float f0 = a_ld[i*4 + u*2], f1 = a_ld[i*4 + u*2 + 1];
                __nv_bfloat16 h0 = __float2bfloat16(f0);
                __nv_bfloat16 h1 = __float2bfloat16(f1);
                __nv_bfloat162 hh; hh.x = h0; hh.y = h1;
                __nv_bfloat162 ll;
                ll.x = __float2bfloat16(f0 - __bfloat162float(h0));
                ll.y = __float2bfloat16(f1 - __bfloat162float(h1));
                hp[u] = *(uint32_t*)&hh; lp[u] = *(uint32_t*)&ll;
            }
            int off = row * 80 + c4 * 8;
            *(uint2*)(base + AH_OFF + off) = make_uint2(hp[0], hp[1]);
            *(uint2*)(base + AL_OFF + off) = make_uint2(lp[0], lp[1]);
        }
#pragma unroll
        for (int i = 0; i < 2; i++) {
            int idx = tid + i * 256;
            int row = idx >> 2, c16 = idx & 3;
            int off = row * 80 + c16 * 16;
            *(uint4*)(base + BH_OFF + off) = bh_ld[i];
            *(uint4*)(base + BL_OFF + off) = bl_ld[i];
        }
    };

    // ---- compute one smem stage ----
    auto compute = [&](int s) {
        const uint32_t stg = smb + s * STG_SZ;
#pragma unroll
        for (int ks = 0; ks < 2; ks++) {
            const int kofs = ks * 16;
            uint32_t ah[4][4], al[4][4], bh[4][2], bl[4][2];
#pragma unroll
            for (int mf = 0; mf < 4; mf++) {
                uint32_t arow = (uint32_t)((wm + mf*16 + aRow) * LDE + kofs + aK) * 2;
                ldm4(ah[mf], stg + AH_OFF + arow);
                ldm4(al[mf], stg + AL_OFF + arow);
            }
#pragma unroll
            for (int g = 0; g < 2; g++) {
                uint32_t brow = (uint32_t)((wn + g*16 + bRow) * LDE + kofs + bK) * 2;
                ldm4(&bh[g*2][0], stg + BH_OFF + brow);
                ldm4(&bl[g*2][0], stg + BL_OFF + brow);
            }
#pragma unroll
            for (int mf = 0; mf < 4; mf++)
#pragma unroll
                for (int nf = 0; nf < 4; nf++) {
                    mma16816(d[mf][nf], ah[mf], bh[nf]);
                    mma16816(d[mf][nf], ah[mf], bl[nf]);
                    mma16816(d[mf][nf], al[mf], bh[nf]);
                }
        }
    };

    // ---- pipelined mainloop ----
    gload(0);
    sstore(0);
    __syncthreads();
    for (int kt = 0; kt < NKT; kt++) {
        const int p = kt & 1;
        if (kt + 1 < NKT) gload(kt + 1);
        compute(p);
        if (kt + 1 < NKT) {
            __syncthreads();
            sstore(p ^ 1);
            __syncthreads();
        }
    }

    // ---- epilogue ----
#pragma unroll
    for (int mf = 0; mf < 4; mf++) {
        const int r0 = bm + wm + mf * 16 + (lane >> 2);
#pragma unroll
        for (int nf = 0; nf < 4; nf++) {
            const int c = bn + wn + nf * 8 + (lane & 3) * 2;
            float2 bv = *(const float2*)(bias + c);
            float2 v0, v1;
            v0.x = d[mf][nf][0] + bv.x;  v0.y = d[mf][nf][1] + bv.y;
            v1.x = d[mf][nf][2] + bv.x;  v1.y = d[mf][nf][3] + bv.y;
            if (GELU) {
                v0.x = gelu_f(v0.x); v0.y = gelu_f(v0.y);
                v1.x = gelu_f(v1.x); v1.y = gelu_f(v1.y);
            }
            const size_t o0 = (size_t)r0 * ldc + c;
            const size_t o1 = (size_t)(r0 + 8) * ldc + c;
            if (res) {
                float2 rr0 = *(const float2*)(res + o0);
                float2 rr1 = *(const float2*)(res + o1);
                v0.x += rr0.x; v0.y += rr0.y;
                v1.x += rr1.x; v1.y += rr1.y;
            }
            *(float2*)(C + o0) = v0;
            *(float2*)(C + o1) = v1;
        }
    }
}

// ---------------- weight transpose + bf16 hi/lo split: W[K,N] -> out[N,K] ----------------
__global__ void __launch_bounds__(256) tsplit_k(
    const float* __restrict__ W, __nv_bfloat16* __restrict__ oh,
    __nv_bfloat16* __restrict__ ol, int K, int N)
{
    __shared__ float tile[32][33];
    int tx = threadIdx.x & 31, ty = threadIdx.x >> 5;   // 32x8
    int n0 = blockIdx.x * 32, k0 = blockIdx.y * 32;
#pragma unroll
    for (int j = 0; j < 4; j++)
        tile[ty + j * 8][tx] = W[(size_t)(k0 + ty + j * 8) * N + n0 + tx];
    __syncthreads();
#pragma unroll
    for (int j = 0; j < 4; j++) {
        int n = n0 + ty + j * 8;
        int k = k0 + tx;
        float f = tile[tx][ty + j * 8];
        __nv_bfloat16 h = __float2bfloat16(f);
        __nv_bfloat16 l = __float2bfloat16(f - __bfloat162float(h));
        oh[(size_t)n * K + k] = h;
        ol[(size_t)n * K + k] = l;
    }
}

// ---------------- pack q/k/v biases into [DEPTH][1536] ----------------
__global__ void packb_k(const float* __restrict__ bq, const float* __restrict__ bk,
                        const float* __restrict__ bv, float* __restrict__ out)
{
    int i = blockIdx.x * blockDim.x + threadIdx.x;
    if (i >= DEPTH * QS) return;
    int l = i / QS, c = i % QS;
    float v;
    if (c < 512)       v = bq[l * 512 + c];
    else if (c < 1024) v = bk[l * 512 + c - 512];
    else               v = bv[l * 512 + c - 1024];
    out[i] = v;
}

// ---------------- LayerNorm ----------------
__global__ void __launch_bounds__(128) ln_k(
    const float* __restrict__ x, const float* __restrict__ g,
    const float* __restrict__ bvec, float* __restrict__ out)
{
    int row = blockIdx.x;
    const float* xr = x + (size_t)row * DD;
    float* orow = out + (size_t)row * DD;
    int tid = threadIdx.x;
    float4 v = *(const float4*)(xr + tid * 4);
    float s  = v.x + v.y + v.z + v.w;
    float sq = v.x*v.x + v.y*v.y + v.z*v.z + v.w*v.w;
#pragma unroll
    for (int off = 16; off; off >>= 1) {
        s  += __shfl_xor_sync(0xffffffffu, s,  off);
        sq += __shfl_xor_sync(0xffffffffu, sq, off);
    }
    __shared__ float ss[4], ssq[4];
    int w = tid >> 5, l = tid & 31;
    if (l == 0) { ss[w] = s; ssq[w] = sq; }
    __syncthreads();
    s  = ss[0] + ss[1] + ss[2] + ss[3];
    sq = ssq[0] + ssq[1] + ssq[2] + ssq[3];
    float mean = s * (1.f / DD);
    float var  = sq * (1.f / DD) - mean * mean;
    float rstd = rsqrtf(var + 1e-5f);
    float4 gv = *(const float4*)(g    + tid * 4);
    float4 bb = *(const float4*)(bvec + tid * 4);
    float4 o;
    o.x = (v.x - mean) * rstd * gv.x + bb.x;
    o.y = (v.y - mean) * rstd * gv.y + bb.y;
    o.z = (v.z - mean) * rstd * gv.z + bb.z;
    o.w = (v.w - mean) * rstd * gv.w + bb.w;
    *(float4*)(orow + tid * 4) = o;
}

// ---------------- box MLP stage 1 ----------------
__global__ void __launch_bounds__(128) box_k(
    const float* __restrict__ boxes, const float* __restrict__ bw1,
    const float* __restrict__ bb1, const float* __restrict__ blg,
    const float* __restrict__ blb, float* __restrict__ out)
{
    int r = blockIdx.x;
    float b0 = boxes[r*4+0], b1 = boxes[r*4+1], b2 = boxes[r*4+2], b3 = boxes[r*4+3];
    int tid = threadIdx.x;
    int d0 = tid * 4;
    float4 w0 = *(const float4*)(bw1 + d0);
    float4 w1 = *(const float4*)(bw1 + 512  + d0);
    float4 w2 = *(const float4*)(bw1 + 1024 + d0);
    float4 w3 = *(const float4*)(bw1 + 1536 + d0);
    float4 bbv = *(const float4*)(bb1 + d0);
    float t[4];
    t[0] = bbv.x + b0*w0.x + b1*w1.x + b2*w2.x + b3*w3.x;
    t[1] = bbv.y + b0*w0.y + b1*w1.y + b2*w2.y + b3*w3.y;
    t[2] = bbv.z + b0*w0.z + b1*w1.z + b2*w2.z + b3*w3.z;
    t[3] = bbv.w + b0*w0.w + b1*w1.w + b2*w2.w + b3*w3.w;
    float s  = t[0]+t[1]+t[2]+t[3];
    float sq = t[0]*t[0]+t[1]*t[1]+t[2]*t[2]+t[3]*t[3];
#pragma unroll
    for (int off = 16; off; off >>= 1) {
        s  += __shfl_xor_sync(0xffffffffu, s,  off);
        sq += __shfl_xor_sync(0xffffffffu, sq, off);
    }
    __shared__ float ss[4], ssq[4];
    int w = tid >> 5, l = tid & 31;
    if (l == 0) { ss[w] = s; ssq[w] = sq; }
    __syncthreads();
    s  = ss[0] + ss[1] + ss[2] + ss[3];
    sq = ssq[0] + ssq[1] + ssq[2] + ssq[3];
    float mean = s * (1.f / DD);
    float var  = sq * (1.f / DD) - mean * mean;
    float rstd = rsqrtf(var + 1e-5f);
    float4 gv = *(const float4*)(blg + d0);
    float4 bv = *(const float4*)(blb + d0);
    float4 o;
    o.x = gelu_f((t[0]-mean)*rstd*gv.x + bv.x);
    o.y = gelu_f((t[1]-mean)*rstd*gv.y + bv.y);
    o.z = gelu_f((t[2]-mean)*rstd*gv.z + bv.z);
    o.w = gelu_f((t[3]-mean)*rstd*gv.w + bv.w);
    *(float4*)(out + (size_t)r * DD + d0) = o;
}

// ---------------- gather obj embeddings ----------------
__global__ void __launch_bounds__(128) gather_k(
    const int* __restrict__ objs, const float* __restrict__ obj_emb,
    float* __restrict__ out)
{
    int r = blockIdx.x;
    int o = objs[r];
    float4 v = *(const float4*)(obj_emb + (size_t)o * DD + threadIdx.x * 4);
    *(float4*)(out + (size_t)r * DD + threadIdx.x * 4) = v;
}

// ---------------- first[i] ----------------
__global__ void first_k(const int* __restrict__ t2i, int* __restrict__ first)
{
    int i = blockIdx.x * blockDim.x + threadIdx.x;
    if (i >= NB) return;
    int lo = 0, hi = NTRI;
    while (lo < hi) {
        int mid = (lo + hi) >> 1;
        if (t2i[mid] < i) lo = mid + 1; else hi = mid;
    }
    first[i] = lo;
}

// ---------------- scatter ----------------
__global__ void __launch_bounds__(128) scatter_k(
    const int* __restrict__ triples, const int* __restrict__ t2i,
    const int* __restrict__ first, const float* __restrict__ objtok,
    const float* __restrict__ pred_emb, float* __restrict__ x,
    unsigned char* __restrict__ mask)
{
    int t = blockIdx.x;
    int j = blockIdx.y;
    int img = t2i[t];
    int pos = t - first[img];
    int slot = pos * 3 + j;
    if (slot >= MT) return;
    const float* src;
    if (j == 0)      src = objtok   + (size_t)triples[t*3+0] * DD;
    else if (j == 1) src = pred_emb + (size_t)triples[t*3+1] * DD;
    else             src = objtok   + (size_t)triples[t*3+2] * DD;
    float* dst = x + ((size_t)img * MT + slot) * DD;
    int tid = threadIdx.x;
    *(float4*)(dst + tid * 4) = *(const float4*)(src + tid * 4);
    if (tid == 0) mask[img * MT + slot] = 1;
}

// ---------------- attention (reads packed qkv, stride QS) ----------------
__global__ void __launch_bounds__(256) attn_k(
    const float* __restrict__ qkv, const unsigned char* __restrict__ mask,
    float* __restrict__ out)
{
    __shared__ float sA[64][65];
    __shared__ float sB[64][65];
    int b = blockIdx.x, h = blockIdx.y;
    int tid = threadIdx.x;
    int tx = tid & 15, ty = tid >> 4;
    const size_t qb = ((size_t)b * MT) * QS + (size_t)h * HD;
    const size_t ob = ((size_t)b * MT) * DD + (size_t)h * HD;

#pragma unroll
    for (int i = 0; i < 16; i++) {
        int idx = tid + i * 256;
        int m = idx >> 6, d = idx & 63;
        sA[m][d] = qkv[qb + (size_t)m * QS + d];          // q
        sB[m][d] = qkv[qb + 512 + (size_t)m * QS + d];    // k
    }
    __syncthreads();

    bool mv[4];
#pragma unroll
    for (int j = 0; j < 4; j++) mv[j] = mask[b * MT + tx * 4 + j] != 0;

    float sc[4][4];
#pragma unroll
    for (int i = 0; i < 4; i++)
#pragma unroll
        for (int j = 0; j < 4; j++) sc[i][j] = 0.f;

    for (int d = 0; d < 64; d++) {
        float a[4], bb[4];
#pragma unroll
        for (int i = 0; i < 4; i++) a[i]  = sA[ty*4+i][d];
#pragma unroll
        for (int j = 0; j < 4; j++) bb[j] = sB[tx*4+j][d];
#pragma unroll
        for (int i = 0; i < 4; i++)
#pragma unroll
            for (int j = 0; j < 4; j++)
                sc[i][j] = fmaf(a[i], bb[j], sc[i][j]);
    }
#pragma unroll
    for (int i = 0; i < 4; i++)
#pragma unroll
        for (int j = 0; j < 4; j++)
            sc[i][j] = mv[j] ? sc[i][j] * 0.125f : -1e9f;

#pragma unroll
    for (int i = 0; i < 4; i++) {
        float mx = fmaxf(fmaxf(sc[i][0], sc[i][1]), fmaxf(sc[i][2], sc[i][3]));
#pragma unroll
        for (int off = 8; off; off >>= 1)
            mx = fmaxf(mx, __shfl_xor_sync(0xffffffffu, mx, off));
        float sum = 0.f;
#pragma unroll
        for (int j = 0; j < 4; j++) { sc[i][j] = expf(sc[i][j] - mx); sum += sc[i][j]; }
#pragma unroll
        for (int off = 8; off; off >>= 1)
            sum += __shfl_xor_sync(0xffffffffu, sum, off);
        float inv = 1.0f / sum;
#pragma unroll
        for (int j = 0; j < 4; j++) sc[i][j] *= inv;
    }
    __syncthreads();

#pragma unroll
    for (int i = 0; i < 4; i++)
#pragma unroll
        for (int j = 0; j < 4; j++)
            sB[ty*4+i][tx*4+j] = sc[i][j];
#pragma unroll
    for (int i = 0; i < 16; i++) {
        int idx = tid + i * 256;
        int m = idx >> 6, d = idx & 63;
        sA[m][d] = qkv[qb + 1024 + (size_t)m * QS + d];   // v
    }
    __syncthreads();

    float o[4][4];
#pragma unroll
    for (int i = 0; i < 4; i++)
#pragma unroll
        for (int j = 0; j < 4; j++) o[i][j] = 0.f;
    for (int kk = 0; kk < 64; kk++) {
        float p[4], vv[4];
#pragma unroll
        for (int i = 0; i < 4; i++) p[i]  = sB[ty*4+i][kk];
#pragma unroll
        for (int j = 0; j < 4; j++) vv[j] = sA[kk][tx*4+j];
#pragma unroll
        for (int i = 0; i < 4; i++)
#pragma unroll
            for (int j = 0; j < 4; j++)
                o[i][j] = fmaf(p[i], vv[j], o[i][j]);
    }
#pragma unroll
    for (int i = 0; i < 4; i++)
#pragma unroll
        for (int j = 0; j < 4; j++)
            out[ob + (size_t)(ty*4+i) * DD + tx*4+j] = o[i][j];
}

// ---------------- host launcher ----------------
extern "C" void kernel_launch(void* const* d_in, const int* in_sizes, int n_in,
                              void* d_out, int out_size)
{
    (void)in_sizes; (void)n_in; (void)out_size;
    const int*   objs    = (const int*)  d_in[0];
    const float* boxes   = (const float*)d_in[1];
    const int*   triples = (const int*)  d_in[2];
    const int*   t2i     = (const int*)  d_in[4];
    const float* obj_emb = (const float*)d_in[5];
    const float* pred_emb= (const float*)d_in[6];
    const float* bw1     = (const float*)d_in[7];
    const float* bb1     = (const float*)d_in[8];
    const float* blg     = (const float*)d_in[9];
    const float* blb     = (const float*)d_in[10];
    const float* bw2     = (const float*)d_in[11];
    const float* bb2     = (const float*)d_in[12];
    const float* ln1g    = (const float*)d_in[13];
    const float* ln1b    = (const float*)d_in[14];
    const float* wq      = (const float*)d_in[15];
    const float* bq      = (const float*)d_in[16];
    const float* wk      = (const float*)d_in[17];
    const float* bk      = (const float*)d_in[18];
    const float* wv      = (const float*)d_in[19];
    const float* bv      = (const float*)d_in[20];
    const float* wo      = (const float*)d_in[21];
    const float* bo      = (const float*)d_in[22];
    const float* ln2g    = (const float*)d_in[23];
    const float* ln2b    = (const float*)d_in[24];
    const float* wf1     = (const float*)d_in[25];
    const float* bf1     = (const float*)d_in[26];
    const float* wf2     = (const float*)d_in[27];
    const float* bf2     = (const float*)d_in[28];
    float* outp = (float*)d_out;

    float *x, *h, *qkv, *attn, *ff, *boxh, *objbase, *objtok, *bqkv;
    __nv_bfloat16 *whi, *wlo;
    unsigned char* mask;
    int* first;
    cudaGetSymbolAddress((void**)&x,       g_x);
    cudaGetSymbolAddress((void**)&h,       g_h);
    cudaGetSymbolAddress((void**)&qkv,     g_qkv);
    cudaGetSymbolAddress((void**)&attn,    g_attn);
    cudaGetSymbolAddress((void**)&ff,      g_ff);
    cudaGetSymbolAddress((void**)&boxh,    g_boxh);
    cudaGetSymbolAddress((void**)&objbase, g_objbase);
    cudaGetSymbolAddress((void**)&objtok,  g_objtok);
    cudaGetSymbolAddress((void**)&mask,    g_mask);
    cudaGetSymbolAddress((void**)&first,   g_first);
    cudaGetSymbolAddress((void**)&whi,     g_whi);
    cudaGetSymbolAddress((void**)&wlo,     g_wlo);
    cudaGetSymbolAddress((void**)&bqkv,    g_bqkv);

    cudaFuncSetAttribute(gemm_mma<false>, cudaFuncAttributeMaxDynamicSharedMemorySize, GSM_TOTAL);
    cudaFuncSetAttribute(gemm_mma<true>,  cudaFuncAttributeMaxDynamicSharedMemorySize, GSM_TOTAL);

    // ---- weight prep: transpose + bf16 hi/lo split ----
    tsplit_k<<<dim3(DD/32, DD/32), 256>>>(bw2, whi + OFF_BW2, wlo + OFF_BW2, DD, DD);
    for (int l = 0; l < DEPTH; l++) {
        size_t wofs = (size_t)l * DD * DD;
        tsplit_k<<<dim3(DD/32, DD/32), 256>>>(wq + wofs, whi + OFF_QKV(l),           wlo + OFF_QKV(l),           DD, DD);
        tsplit_k<<<dim3(DD/32, DD/32), 256>>>(wk + wofs, whi + OFF_QKV(l) + 262144,  wlo + OFF_QKV(l) + 262144,  DD, DD);
        tsplit_k<<<dim3(DD/32, DD/32), 256>>>(wv + wofs, whi + OFF_QKV(l) + 524288,  wlo + OFF_QKV(l) + 524288,  DD, DD);
        tsplit_k<<<dim3(DD/32, DD/32), 256>>>(wo + wofs, whi + OFF_WO(l),            wlo + OFF_WO(l),            DD, DD);
        tsplit_k<<<dim3(FF/32, DD/32), 256>>>(wf1 + (size_t)l*DD*FF, whi + OFF_F1(l), wlo + OFF_F1(l), DD, FF);
        tsplit_k<<<dim3(DD/32, FF/32), 256>>>(wf2 + (size_t)l*FF*DD, whi + OFF_F2(l), wlo + OFF_F2(l), FF, DD);
    }
    packb_k<<<(DEPTH*QS + 255)/256, 256>>>(bq, bk, bv, bqkv);

    // ---- prologue ----
    box_k<<<NOBJ, 128>>>(boxes, bw1, bb1, blg, blb, boxh);
    gather_k<<<NOBJ, 128>>>(objs, obj_emb, objbase);
    gemm_mma<false><<<dim3(DD/BN, NOBJ/BM), 256, GSM_TOTAL>>>(
        boxh, whi + OFF_BW2, wlo + OFF_BW2, bb2, objbase, objtok, DD, DD);
    first_k<<<(NB + 127)/128, 128>>>(t2i, first);
    cudaMemsetAsync(x, 0, (size_t)BMT * DD * sizeof(float));
    cudaMemsetAsync(mask, 0, BMT);
    scatter_k<<<dim3(NTRI, 3), 128>>>(triples, t2i, first, objtok, pred_emb, x, mask);

    // ---- transformer layers ----
    const dim3 gQKV(QS/BN, BMT/BM);   // (12, 512)
    const dim3 gD  (DD/BN, BMT/BM);   // (4, 512)
    const dim3 gF1 (FF/BN, BMT/BM);   // (16, 512)
    for (int l = 0; l < DEPTH; l++) {
        ln_k<<<BMT, 128>>>(x, ln1g + l*DD, ln1b + l*DD, h);
        gemm_mma<false><<<gQKV, 256, GSM_TOTAL>>>(
            h, whi + OFF_QKV(l), wlo + OFF_QKV(l), bqkv + l*QS, nullptr, qkv, DD, QS);
        attn_k<<<dim3(NB, NH), 256>>>(qkv, mask, attn);
        gemm_mma<false><<<gD, 256, GSM_TOTAL>>>(
            attn, whi + OFF_WO(l), wlo + OFF_WO(l), bo + l*DD, x, x, DD, DD);
        ln_k<<<BMT, 128>>>(x, ln2g + l*DD, ln2b + l*DD, h);
        gemm_mma<true><<<gF1, 256, GSM_TOTAL>>>(
            h, whi + OFF_F1(l), wlo + OFF_F1(l), bf1 + l*FF, nullptr, ff, DD, FF);
        float* cdst = (l == DEPTH - 1) ? outp : x;
        gemm_mma<false><<<gD, 256, GSM_TOTAL>>>(
            ff, whi + OFF_F2(l), wlo + OFF_F2(l), bf2 + l*DD, x, cdst, FF, DD);
    }
}

// round 7
// speedup vs baseline: 2.5011x; 1.0248x over previous
#include <cuda_runtime.h>
#include <cuda_bf16.h>
#include <math.h>
#include <stdint.h>

// ---------------- problem constants ----------------
#define NB    1024
#define MT    64
#define DD    512
#define NH    8
#define HD    64
#define DEPTH 4
#define FF    2048
#define NOBJ  8192
#define NTRI  10240
#define BMT   (NB*MT)   // 65536 rows
#define QS    1536      // packed qkv row stride

// ---------------- static scratch ----------------
#define W_TOT 12845056   // 512*512 + 4*(1536*512 + 512*512 + 2048*512 + 512*2048)
__device__ __nv_bfloat16 g_whi[W_TOT];
__device__ __nv_bfloat16 g_wlo[W_TOT];
__device__ float g_bqkv[DEPTH*QS];
__device__ float g_x   [BMT*DD];
__device__ __nv_bfloat16 g_hhi[BMT*DD];
__device__ __nv_bfloat16 g_hlo[BMT*DD];
__device__ float g_qkv [(size_t)BMT*QS];
__device__ __nv_bfloat16 g_athi[BMT*DD];
__device__ __nv_bfloat16 g_atlo[BMT*DD];
__device__ __nv_bfloat16 g_ffhi[(size_t)BMT*FF];
__device__ __nv_bfloat16 g_fflo[(size_t)BMT*FF];
__device__ __nv_bfloat16 g_bxhi[NOBJ*DD];
__device__ __nv_bfloat16 g_bxlo[NOBJ*DD];
__device__ float g_objbase[NOBJ*DD];
__device__ float g_objtok [NOBJ*DD];
__device__ unsigned char g_mask[BMT];
__device__ int   g_first[NB];

// weight pool offsets (bf16 elements)
#define OFF_BW2 0
#define LYR_STRIDE 3145728
#define OFF_L(l)   (262144 + (l)*LYR_STRIDE)
#define OFF_QKV(l) OFF_L(l)
#define OFF_WO(l)  (OFF_L(l)+786432)
#define OFF_F1(l)  (OFF_L(l)+1048576)
#define OFF_F2(l)  (OFF_L(l)+2097152)

__device__ __forceinline__ float gelu_f(float x) {
    return 0.5f * x * (1.0f + erff(x * 0.70710678118654752440f));
}
__device__ __forceinline__ uint32_t smem_u32(const void* p) {
    uint32_t a;
    asm("{ .reg .u64 t; cvta.to.shared.u64 t, %1; cvt.u32.u64 %0, t; }" : "=r"(a) : "l"(p));
    return a;
}
__device__ __forceinline__ void split2(float v0, float v1, uint32_t& hi, uint32_t& lo) {
    __nv_bfloat162 hh, ll;
    hh.x = __float2bfloat16(v0);
    hh.y = __float2bfloat16(v1);
    ll.x = __float2bfloat16(v0 - __bfloat162float(hh.x));
    ll.y = __float2bfloat16(v1 - __bfloat162float(hh.y));
    hi = *(uint32_t*)&hh; lo = *(uint32_t*)&ll;
}

// ---------------- warp-level MMA primitives (family-wide, sm_80+) ----------------
__device__ __forceinline__ void ldm4(uint32_t* r, uint32_t addr) {
    asm volatile("ldmatrix.sync.aligned.m8n8.x4.shared.b16 {%0,%1,%2,%3}, [%4];"
        : "=r"(r[0]), "=r"(r[1]), "=r"(r[2]), "=r"(r[3]) : "r"(addr));
}
__device__ __forceinline__ void mma16816(float* d, const uint32_t* a, const uint32_t* b) {
    asm volatile("mma.sync.aligned.m16n8k16.row.col.f32.bf16.bf16.f32 "
        "{%0,%1,%2,%3}, {%4,%5,%6,%7}, {%8,%9}, {%0,%1,%2,%3};"
        : "+f"(d[0]), "+f"(d[1]), "+f"(d[2]), "+f"(d[3])
        : "r"(a[0]), "r"(a[1]), "r"(a[2]), "r"(a[3]), "r"(b[0]), "r"(b[1]));
}
__device__ __forceinline__ void cpasync16(uint32_t sdst, const void* gsrc) {
    asm volatile("cp.async.cg.shared.global [%0], [%1], 16;" :: "r"(sdst), "l"(gsrc));
}
#define CP_COMMIT() asm volatile("cp.async.commit_group;" ::: "memory")
#define CP_WAIT1()  asm volatile("cp.async.wait_group 1;" ::: "memory")

// ---------------- GEMM: mma.sync bf16 3-term split, pre-split inputs ----------------
// C[M,N] = (Ahi+Alo)[M,K] @ (Bhi+Blo)^T[N,K] (3 terms) + bias (+gelu) (+res | split-out)
// Tile 128x256, BK=32, 8 warps (2x4), warp tile 64x64, 3-stage cp.async pipeline.
#define BM 128
#define BN 256
#define BK 32
#define LDE 40            // padded smem row stride in bf16 elements (80 B)
#define A_HI 0
#define A_LO 10240
#define B_HI 20480
#define B_LO 40960
#define STG_SZ 61440
#define NSTG 3
#define GSM_TOTAL (NSTG*STG_SZ)   // 184320 B

template<bool GELU, bool SPLITOUT>
__global__ void __launch_bounds__(256, 1) gemm2(
    const __nv_bfloat16* __restrict__ Ahi, const __nv_bfloat16* __restrict__ Alo,
    const __nv_bfloat16* __restrict__ Bhi, const __nv_bfloat16* __restrict__ Blo,
    const float* __restrict__ bias, const float* __restrict__ res,
    float* __restrict__ C, __nv_bfloat16* __restrict__ Chi, __nv_bfloat16* __restrict__ Clo,
    int K, int ldc)
{
    extern __shared__ char sm[];
    const uint32_t smb = smem_u32(sm);
    const int tid  = threadIdx.x;
    const int lane = tid & 31;
    const int wid  = tid >> 5;
    const int wm   = (wid & 1) * 64;
    const int wn   = (wid >> 1) * 64;
    const int bn   = blockIdx.x * BN;
    const int bm   = blockIdx.y * BM;

    const int aRow = lane & 15;
    const int aK   = (lane >> 4) << 3;
    const int bRow = (lane & 7) + ((lane >> 4) << 3);
    const int bK   = ((lane >> 3) & 1) << 3;

    float d[4][8][4];
#pragma unroll
    for (int i = 0; i < 4; i++)
#pragma unroll
        for (int j = 0; j < 8; j++)
#pragma unroll
            for (int u = 0; u < 4; u++) d[i][j][u] = 0.f;

    const int NKT = K >> 5;

    // per-thread load coordinates (16B chunks)
    const int arow = tid >> 2, acol = tid & 3;          // +i*64 rows
    // (B uses same decomposition, 4 iterations)

    auto load_stage = [&](int kt, int s) {
        const uint32_t stg = smb + (uint32_t)s * STG_SZ;
        const int k0 = kt << 5;
#pragma unroll
        for (int i = 0; i < 2; i++) {
            int row = arow + i * 64;
            size_t g = (size_t)(bm + row) * K + k0 + acol * 8;
            uint32_t so = (uint32_t)(row * 80 + acol * 16);
            cpasync16(stg + A_HI + so, Ahi + g);
            cpasync16(stg + A_LO + so, Alo + g);
        }
#pragma unroll
        for (int i = 0; i < 4; i++) {
            int row = arow + i * 64;
            size_t g = (size_t)(bn + row) * K + k0 + acol * 8;
            uint32_t so = (uint32_t)(row * 80 + acol * 16);
            cpasync16(stg + B_HI + so, Bhi + g);
            cpasync16(stg + B_LO + so, Blo + g);
        }
    };

    auto compute = [&](int s) {
        const uint32_t stg = smb + (uint32_t)s * STG_SZ;
#pragma unroll
        for (int ks = 0; ks < 2; ks++) {
            const int kofs = ks * 16;
            uint32_t ah[4][4], al[4][4], bh[4][4], bl[4][4];
#pragma unroll
            for (int mf = 0; mf < 4; mf++) {
                uint32_t ao = (uint32_t)((wm + mf*16 + aRow) * LDE + kofs + aK) * 2;
                ldm4(ah[mf], stg + A_HI + ao);
                ldm4(al[mf], stg + A_LO + ao);
            }
#pragma unroll
            for (int g = 0; g < 4; g++) {
                uint32_t bo = (uint32_t)((wn + g*16 + bRow) * LDE + kofs + bK) * 2;
                ldm4(bh[g], stg + B_HI + bo);
                ldm4(bl[g], stg + B_LO + bo);
            }
#pragma unroll
            for (int mf = 0; mf < 4; mf++)
#pragma unroll
                for (int nf = 0; nf < 8; nf++)
                    mma16816(d[mf][nf], ah[mf], &bh[nf >> 1][(nf & 1) * 2]);
#pragma unroll
            for (int mf = 0; mf < 4; mf++)
#pragma unroll
                for (int nf = 0; nf < 8; nf++)
                    mma16816(d[mf][nf], ah[mf], &bl[nf >> 1][(nf & 1) * 2]);
#pragma unroll
            for (int mf = 0; mf < 4; mf++)
#pragma unroll
                for (int nf = 0; nf < 8; nf++)
                    mma16816(d[mf][nf], al[mf], &bh[nf >> 1][(nf & 1) * 2]);
        }
    };

    // ---- 3-stage pipeline ----
    load_stage(0, 0); CP_COMMIT();
    load_stage(1, 1); CP_COMMIT();
    int sidx = 2;
    for (int kt = 0; kt < NKT; kt++) {
        CP_WAIT1();
        __syncthreads();
        if (kt + 2 < NKT) {
            load_stage(kt + 2, sidx);
            sidx = (sidx + 1) % 3;
        }
        CP_COMMIT();
        compute(kt % 3);
    }

    // ---- epilogue ----
#pragma unroll
    for (int mf = 0; mf < 4; mf++) {
        const int r0 = bm + wm + mf * 16 + (lane >> 2);
#pragma unroll
        for (int nf = 0; nf < 8; nf++) {
            const int c = bn + wn + nf * 8 + (lane & 3) * 2;
            float2 bv = *(const float2*)(bias + c);
            float v00 = d[mf][nf][0] + bv.x, v01 = d[mf][nf][1] + bv.y;
            float v10 = d[mf][nf][2] + bv.x, v11 = d[mf][nf][3] + bv.y;
            if (GELU) {
                v00 = gelu_f(v00); v01 = gelu_f(v01);
                v10 = gelu_f(v10); v11 = gelu_f(v11);
            }
            const size_t o0 = (size_t)r0 * ldc + c;
            const size_t o1 = (size_t)(r0 + 8) * ldc + c;
            if (SPLITOUT) {
                uint32_t h0, l0, h1, l1;
                split2(v00, v01, h0, l0);
                split2(v10, v11, h1, l1);
                *(uint32_t*)(Chi + o0) = h0;
                *(uint32_t*)(Clo + o0) = l0;
                *(uint32_t*)(Chi + o1) = h1;
                *(uint32_t*)(Clo + o1) = l1;
            } else {
                float2 w0 = make_float2(v00, v01);
                float2 w1 = make_float2(v10, v11);
                if (res) {
                    float2 rr0 = *(const float2*)(res + o0);
                    float2 rr1 = *(const float2*)(res + o1);
                    w0.x += rr0.x; w0.y += rr0.y;
                    w1.x += rr1.x; w1.y += rr1.y;
                }
                *(float2*)(C + o0) = w0;
                *(float2*)(C + o1) = w1;
            }
        }
    }
}

// ---------------- weight transpose + bf16 hi/lo split: W[K,N] -> out[N,K] ----------------
__global__ void __launch_bounds__(256) tsplit_k(
    const float* __restrict__ W, __nv_bfloat16* __restrict__ oh,
    __nv_bfloat16* __restrict__ ol, int K, int N)
{
    __shared__ float tile[32][33];
    int tx = threadIdx.x & 31, ty = threadIdx.x >> 5;
    int n0 = blockIdx.x * 32, k0 = blockIdx.y * 32;
#pragma unroll
    for (int j = 0; j < 4; j++)
        tile[ty + j * 8][tx] = W[(size_t)(k0 + ty + j * 8) * N + n0 + tx];
    __syncthreads();
#pragma unroll
    for (int j = 0; j < 4; j++) {
        int n = n0 + ty + j * 8;
        int k = k0 + tx;
        float f = tile[tx][ty + j * 8];
        __nv_bfloat16 h = __float2bfloat16(f);
        __nv_bfloat16 l = __float2bfloat16(f - __bfloat162float(h));
        oh[(size_t)n * K + k] = h;
        ol[(size_t)n * K + k] = l;
    }
}

// ---------------- pack q/k/v biases ----------------
__global__ void packb_k(const float* __restrict__ bq, const float* __restrict__ bk,
                        const float* __restrict__ bv, float* __restrict__ out)
{
    int i = blockIdx.x * blockDim.x + threadIdx.x;
    if (i >= DEPTH * QS) return;
    int l = i / QS, c = i % QS;
    float v;
    if (c < 512)       v = bq[l * 512 + c];
    else if (c < 1024) v = bk[l * 512 + c - 512];
    else               v = bv[l * 512 + c - 1024];
    out[i] = v;
}

// ---------------- LayerNorm, split-out ----------------
__global__ void __launch_bounds__(128) ln_k(
    const float* __restrict__ x, const float* __restrict__ g,
    const float* __restrict__ bvec,
    __nv_bfloat16* __restrict__ ohi, __nv_bfloat16* __restrict__ olo)
{
    int row = blockIdx.x;
    const float* xr = x + (size_t)row * DD;
    int tid = threadIdx.x;
    float4 v = *(const float4*)(xr + tid * 4);
    float s  = v.x + v.y + v.z + v.w;
    float sq = v.x*v.x + v.y*v.y + v.z*v.z + v.w*v.w;
#pragma unroll
    for (int off = 16; off; off >>= 1) {
        s  += __shfl_xor_sync(0xffffffffu, s,  off);
        sq += __shfl_xor_sync(0xffffffffu, sq, off);
    }
    __shared__ float ss[4], ssq[4];
    int w = tid >> 5, l = tid & 31;
    if (l == 0) { ss[w] = s; ssq[w] = sq; }
    __syncthreads();
    s  = ss[0] + ss[1] + ss[2] + ss[3];
    sq = ssq[0] + ssq[1] + ssq[2] + ssq[3];
    float mean = s * (1.f / DD);
    float var  = sq * (1.f / DD) - mean * mean;
    float rstd = rsqrtf(var + 1e-5f);
    float4 gv = *(const float4*)(g    + tid * 4);
    float4 bb = *(const float4*)(bvec + tid * 4);
    float o0 = (v.x - mean) * rstd * gv.x + bb.x;
    float o1 = (v.y - mean) * rstd * gv.y + bb.y;
    float o2 = (v.z - mean) * rstd * gv.z + bb.z;
    float o3 = (v.w - mean) * rstd * gv.w + bb.w;
    uint32_t h0, l0, h1, l1;
    split2(o0, o1, h0, l0);
    split2(o2, o3, h1, l1);
    size_t ob = (size_t)row * DD + tid * 4;
    *(uint32_t*)(ohi + ob)     = h0;
    *(uint32_t*)(ohi + ob + 2) = h1;
    *(uint32_t*)(olo + ob)     = l0;
    *(uint32_t*)(olo + ob + 2) = l1;
}

// ---------------- box MLP stage 1, split-out ----------------
__global__ void __launch_bounds__(128) box_k(
    const float* __restrict__ boxes, const float* __restrict__ bw1,
    const float* __restrict__ bb1, const float* __restrict__ blg,
    const float* __restrict__ blb,
    __nv_bfloat16* __restrict__ ohi, __nv_bfloat16* __restrict__ olo)
{
    int r = blockIdx.x;
    float b0 = boxes[r*4+0], b1 = boxes[r*4+1], b2 = boxes[r*4+2], b3 = boxes[r*4+3];
    int tid = threadIdx.x;
    int d0 = tid * 4;
    float4 w0 = *(const float4*)(bw1 + d0);
    float4 w1 = *(const float4*)(bw1 + 512  + d0);
    float4 w2 = *(const float4*)(bw1 + 1024 + d0);
    float4 w3 = *(const float4*)(bw1 + 1536 + d0);
    float4 bbv = *(const float4*)(bb1 + d0);
    float t[4];
    t[0] = bbv.x + b0*w0.x + b1*w1.x + b2*w2.x + b3*w3.x;
    t[1] = bbv.y + b0*w0.y + b1*w1.y + b2*w2.y + b3*w3.y;
    t[2] = bbv.z + b0*w0.z + b1*w1.z + b2*w2.z + b3*w3.z;
    t[3] = bbv.w + b0*w0.w + b1*w1.w + b2*w2.w + b3*w3.w;
    float s  = t[0]+t[1]+t[2]+t[3];
    float sq = t[0]*t[0]+t[1]*t[1]+t[2]*t[2]+t[3]*t[3];
#pragma unroll
    for (int off = 16; off; off >>= 1) {
        s  += __shfl_xor_sync(0xffffffffu, s,  off);
        sq += __shfl_xor_sync(0xffffffffu, sq, off);
    }
    __shared__ float ss[4], ssq[4];
    int w = tid >> 5, l = tid & 31;
    if (l == 0) { ss[w] = s; ssq[w] = sq; }
    __syncthreads();
    s  = ss[0] + ss[1] + ss[2] + ss[3];
    sq = ssq[0] + ssq[1] + ssq[2] + ssq[3];
    float mean = s * (1.f / DD);
    float var  = sq * (1.f / DD) - mean * mean;
    float rstd = rsqrtf(var + 1e-5f);
    float4 gv = *(const float4*)(blg + d0);
    float4 bv = *(const float4*)(blb + d0);
    float o0 = gelu_f((t[0]-mean)*rstd*gv.x + bv.x);
    float o1 = gelu_f((t[1]-mean)*rstd*gv.y + bv.y);
    float o2 = gelu_f((t[2]-mean)*rstd*gv.z + bv.z);
    float o3 = gelu_f((t[3]-mean)*rstd*gv.w + bv.w);
    uint32_t h0, l0, h1, l1;
    split2(o0, o1, h0, l0);
    split2(o2, o3, h1, l1);
    size_t ob = (size_t)r * DD + d0;
    *(uint32_t*)(ohi + ob)     = h0;
    *(uint32_t*)(ohi + ob + 2) = h1;
    *(uint32_t*)(olo + ob)     = l0;
    *(uint32_t*)(olo + ob + 2) = l1;
}

// ---------------- gather obj embeddings ----------------
__global__ void __launch_bounds__(128) gather_k(
    const int* __restrict__ objs, const float* __restrict__ obj_emb,
    float* __restrict__ out)
{
    int r = blockIdx.x;
    int o = objs[r];
    float4 v = *(const float4*)(obj_emb + (size_t)o * DD + threadIdx.x * 4);
    *(float4*)(out + (size_t)r * DD + threadIdx.x * 4) = v;
}

// ---------------- first[i] ----------------
__global__ void first_k(const int* __restrict__ t2i, int* __restrict__ first)
{
    int i = blockIdx.x * blockDim.x + threadIdx.x;
    if (i >= NB) return;
    int lo = 0, hi = NTRI;
    while (lo < hi) {
        int mid = (lo + hi) >> 1;
        if (t2i[mid] < i) lo = mid + 1; else hi = mid;
    }
    first[i] = lo;
}

// ---------------- scatter ----------------
__global__ void __launch_bounds__(128) scatter_k(
    const int* __restrict__ triples, const int* __restrict__ t2i,
    const int* __restrict__ first, const float* __restrict__ objtok,
    const float* __restrict__ pred_emb, float* __restrict__ x,
    unsigned char* __restrict__ mask)
{
    int t = blockIdx.x;
    int j = blockIdx.y;
    int img = t2i[t];
    int pos = t - first[img];
    int slot = pos * 3 + j;
    if (slot >= MT) return;
    const float* src;
    if (j == 0)      src = objtok   + (size_t)triples[t*3+0] * DD;
    else if (j == 1) src = pred_emb + (size_t)triples[t*3+1] * DD;
    else             src = objtok   + (size_t)triples[t*3+2] * DD;
    float* dst = x + ((size_t)img * MT + slot) * DD;
    int tid = threadIdx.x;
    *(float4*)(dst + tid * 4) = *(const float4*)(src + tid * 4);
    if (tid == 0) mask[img * MT + slot] = 1;
}

// ---------------- attention (reads packed qkv fp32, writes split bf16) ----------------
__global__ void __launch_bounds__(256) attn_k(
    const float* __restrict__ qkv, const unsigned char* __restrict__ mask,
    __nv_bfloat16* __restrict__ ohi, __nv_bfloat16* __restrict__ olo)
{
    __shared__ float sA[64][65];
    __shared__ float sB[64][65];
    int b = blockIdx.x, h = blockIdx.y;
    int tid = threadIdx.x;
    int tx = tid & 15, ty = tid >> 4;
    const size_t qb = ((size_t)b * MT) * QS + (size_t)h * HD;
    const size_t ob = ((size_t)b * MT) * DD + (size_t)h * HD;

#pragma unroll
    for (int i = 0; i < 16; i++) {
        int idx = tid + i * 256;
        int m = idx >> 6, dd = idx & 63;
        sA[m][dd] = qkv[qb + (size_t)m * QS + dd];
        sB[m][dd] = qkv[qb + 512 + (size_t)m * QS + dd];
    }
    __syncthreads();

    bool mv[4];
#pragma unroll
    for (int j = 0; j < 4; j++) mv[j] = mask[b * MT + tx * 4 + j] != 0;

    float sc[4][4];
#pragma unroll
    for (int i = 0; i < 4; i++)
#pragma unroll
        for (int j = 0; j < 4; j++) sc[i][j] = 0.f;

    for (int dd = 0; dd < 64; dd++) {
        float a[4], bb[4];
#pragma unroll
        for (int i = 0; i < 4; i++) a[i]  = sA[ty*4+i][dd];
#pragma unroll
        for (int j = 0; j < 4; j++) bb[j] = sB[tx*4+j][dd];
#pragma unroll
        for (int i = 0; i < 4; i++)
#pragma unroll
            for (int j = 0; j < 4; j++)
                sc[i][j] = fmaf(a[i], bb[j], sc[i][j]);
    }
#pragma unroll
    for (int i = 0; i < 4; i++)
#pragma unroll
        for (int j = 0; j < 4; j++)
            sc[i][j] = mv[j] ? sc[i][j] * 0.125f : -1e9f;

#pragma unroll
    for (int i = 0; i < 4; i++) {
        float mx = fmaxf(fmaxf(sc[i][0], sc[i][1]), fmaxf(sc[i][2], sc[i][3]));
#pragma unroll
        for (int off = 8; off; off >>= 1)
            mx = fmaxf(mx, __shfl_xor_sync(0xffffffffu, mx, off));
        float sum = 0.f;
#pragma unroll
        for (int j = 0; j < 4; j++) { sc[i][j] = expf(sc[i][j] - mx); sum += sc[i][j]; }
#pragma unroll
        for (int off = 8; off; off >>= 1)
            sum += __shfl_xor_sync(0xffffffffu, sum, off);
        float inv = 1.0f / sum;
#pragma unroll
        for (int j = 0; j < 4; j++) sc[i][j] *= inv;
    }
    __syncthreads();

#pragma unroll
    for (int i = 0; i < 4; i++)
#pragma unroll
        for (int j = 0; j < 4; j++)
            sB[ty*4+i][tx*4+j] = sc[i][j];
#pragma unroll
    for (int i = 0; i < 16; i++) {
        int idx = tid + i * 256;
        int m = idx >> 6, dd = idx & 63;
        sA[m][dd] = qkv[qb + 1024 + (size_t)m * QS + dd];
    }
    __syncthreads();

    float o[4][4];
#pragma unroll
    for (int i = 0; i < 4; i++)
#pragma unroll
        for (int j = 0; j < 4; j++) o[i][j] = 0.f;
    for (int kk = 0; kk < 64; kk++) {
        float p[4], vv[4];
#pragma unroll
        for (int i = 0; i < 4; i++) p[i]  = sB[ty*4+i][kk];
#pragma unroll
        for (int j = 0; j < 4; j++) vv[j] = sA[kk][tx*4+j];
#pragma unroll
        for (int i = 0; i < 4; i++)
#pragma unroll
            for (int j = 0; j < 4; j++)
                o[i][j] = fmaf(p[i], vv[j], o[i][j]);
    }
#pragma unroll
    for (int i = 0; i < 4; i++) {
        size_t ro = ob + (size_t)(ty*4+i) * DD + tx*4;
        uint32_t h0, l0, h1, l1;
        split2(o[i][0], o[i][1], h0, l0);
        split2(o[i][2], o[i][3], h1, l1);
        *(uint32_t*)(ohi + ro)     = h0;
        *(uint32_t*)(ohi + ro + 2) = h1;
        *(uint32_t*)(olo + ro)     = l0;
        *(uint32_t*)(olo + ro + 2) = l1;
    }
}

// ---------------- host launcher ----------------
extern "C" void kernel_launch(void* const* d_in, const int* in_sizes, int n_in,
                              void* d_out, int out_size)
{
    (void)in_sizes; (void)n_in; (void)out_size;
    const int*   objs    = (const int*)  d_in[0];
    const float* boxes   = (const float*)d_in[1];
    const int*   triples = (const int*)  d_in[2];
    const int*   t2i     = (const int*)  d_in[4];
    const float* obj_emb = (const float*)d_in[5];
    const float* pred_emb= (const float*)d_in[6];
    const float* bw1     = (const float*)d_in[7];
    const float* bb1     = (const float*)d_in[8];
    const float* blg     = (const float*)d_in[9];
    const float* blb     = (const float*)d_in[10];
    const float* bw2     = (const float*)d_in[11];
    const float* bb2     = (const float*)d_in[12];
    const float* ln1g    = (const float*)d_in[13];
    const float* ln1b    = (const float*)d_in[14];
    const float* wq      = (const float*)d_in[15];
    const float* bq      = (const float*)d_in[16];
    const float* wk      = (const float*)d_in[17];
    const float* bk      = (const float*)d_in[18];
    const float* wv      = (const float*)d_in[19];
    const float* bv      = (const float*)d_in[20];
    const float* wo      = (const float*)d_in[21];
    const float* bo      = (const float*)d_in[22];
    const float* ln2g    = (const float*)d_in[23];
    const float* ln2b    = (const float*)d_in[24];
    const float* wf1     = (const float*)d_in[25];
    const float* bf1     = (const float*)d_in[26];
    const float* wf2     = (const float*)d_in[27];
    const float* bf2     = (const float*)d_in[28];
    float* outp = (float*)d_out;

    float *x, *qkv, *objbase, *objtok, *bqkv;
    __nv_bfloat16 *whi, *wlo, *hhi, *hlo, *athi, *atlo, *ffhi, *fflo, *bxhi, *bxlo;
    unsigned char* mask;
    int* first;
    cudaGetSymbolAddress((void**)&x,       g_x);
    cudaGetSymbolAddress((void**)&qkv,     g_qkv);
    cudaGetSymbolAddress((void**)&objbase, g_objbase);
    cudaGetSymbolAddress((void**)&objtok,  g_objtok);
    cudaGetSymbolAddress((void**)&mask,    g_mask);
    cudaGetSymbolAddress((void**)&first,   g_first);
    cudaGetSymbolAddress((void**)&whi,     g_whi);
    cudaGetSymbolAddress((void**)&wlo,     g_wlo);
    cudaGetSymbolAddress((void**)&bqkv,    g_bqkv);
    cudaGetSymbolAddress((void**)&hhi,     g_hhi);
    cudaGetSymbolAddress((void**)&hlo,     g_hlo);
    cudaGetSymbolAddress((void**)&athi,    g_athi);
    cudaGetSymbolAddress((void**)&atlo,    g_atlo);
    cudaGetSymbolAddress((void**)&ffhi,    g_ffhi);
    cudaGetSymbolAddress((void**)&fflo,    g_fflo);
    cudaGetSymbolAddress((void**)&bxhi,    g_bxhi);
    cudaGetSymbolAddress((void**)&bxlo,    g_bxlo);

    cudaFuncSetAttribute(gemm2<false,false>, cudaFuncAttributeMaxDynamicSharedMemorySize, GSM_TOTAL);
    cudaFuncSetAttribute(gemm2<true,true>,   cudaFuncAttributeMaxDynamicSharedMemorySize, GSM_TOTAL);

    // ---- weight prep: transpose + bf16 hi/lo split ----
    tsplit_k<<<dim3(DD/32, DD/32), 256>>>(bw2, whi + OFF_BW2, wlo + OFF_BW2, DD, DD);
    for (int l = 0; l < DEPTH; l++) {
        size_t wofs = (size_t)l * DD * DD;
        tsplit_k<<<dim3(DD/32, DD/32), 256>>>(wq + wofs, whi + OFF_QKV(l),           wlo + OFF_QKV(l),           DD, DD);
        tsplit_k<<<dim3(DD/32, DD/32), 256>>>(wk + wofs, whi + OFF_QKV(l) + 262144,  wlo + OFF_QKV(l) + 262144,  DD, DD);
        tsplit_k<<<dim3(DD/32, DD/32), 256>>>(wv + wofs, whi + OFF_QKV(l) + 524288,  wlo + OFF_QKV(l) + 524288,  DD, DD);
        tsplit_k<<<dim3(DD/32, DD/32), 256>>>(wo + wofs, whi + OFF_WO(l),            wlo + OFF_WO(l),            DD, DD);
        tsplit_k<<<dim3(FF/32, DD/32), 256>>>(wf1 + (size_t)l*DD*FF, whi + OFF_F1(l), wlo + OFF_F1(l), DD, FF);
        tsplit_k<<<dim3(DD/32, FF/32), 256>>>(wf2 + (size_t)l*FF*DD, whi + OFF_F2(l), wlo + OFF_F2(l), FF, DD);
    }
    packb_k<<<(DEPTH*QS + 255)/256, 256>>>(bq, bk, bv, bqkv);

    // ---- prologue ----
    box_k<<<NOBJ, 128>>>(boxes, bw1, bb1, blg, blb, bxhi, bxlo);
    gather_k<<<NOBJ, 128>>>(objs, obj_emb, objbase);
    gemm2<false,false><<<dim3(DD/BN, NOBJ/BM), 256, GSM_TOTAL>>>(
        bxhi, bxlo, whi + OFF_BW2, wlo + OFF_BW2, bb2, objbase, objtok, nullptr, nullptr, DD, DD);
    first_k<<<(NB + 127)/128, 128>>>(t2i, first);
    cudaMemsetAsync(x, 0, (size_t)BMT * DD * sizeof(float));
    cudaMemsetAsync(mask, 0, BMT);
    scatter_k<<<dim3(NTRI, 3), 128>>>(triples, t2i, first, objtok, pred_emb, x, mask);

    // ---- transformer layers ----
    const dim3 gQKV(QS/BN, BMT/BM);   // (6, 512)
    const dim3 gD  (DD/BN, BMT/BM);   // (2, 512)
    const dim3 gF1 (FF/BN, BMT/BM);   // (8, 512)
    for (int l = 0; l < DEPTH; l++) {
        ln_k<<<BMT, 128>>>(x, ln1g + l*DD, ln1b + l*DD, hhi, hlo);
        gemm2<false,false><<<gQKV, 256, GSM_TOTAL>>>(
            hhi, hlo, whi + OFF_QKV(l), wlo + OFF_QKV(l), bqkv + l*QS,
            nullptr, qkv, nullptr, nullptr, DD, QS);
        attn_k<<<dim3(NB, NH), 256>>>(qkv, mask, athi, atlo);
        gemm2<false,false><<<gD, 256, GSM_TOTAL>>>(
            athi, atlo, whi + OFF_WO(l), wlo + OFF_WO(l), bo + l*DD,
            x, x, nullptr, nullptr, DD, DD);
        ln_k<<<BMT, 128>>>(x, ln2g + l*DD, ln2b + l*DD, hhi, hlo);
        gemm2<true,true><<<gF1, 256, GSM_TOTAL>>>(
            hhi, hlo, whi + OFF_F1(l), wlo + OFF_F1(l), bf1 + l*FF,
            nullptr, nullptr, ffhi, fflo, DD, FF);
        float* cdst = (l == DEPTH - 1) ? outp : x;
        gemm2<false,false><<<gD, 256, GSM_TOTAL>>>(
            ffhi, fflo, whi + OFF_F2(l), wlo + OFF_F2(l), bf2 + l*DD,
            x, cdst, nullptr, nullptr, FF, DD);
    }
}